// round 12
// baseline (speedup 1.0000x reference)
#include <cuda_runtime.h>
#include <cuda_bf16.h>
#include <cuda_fp8.h>
#include <cstdint>

// ---------------------------------------------------------------------------
// loss2, 3 launches (resubmission of R11 — prior round was an infra failure,
// the kernel never ran):
//   1) normalize -> e4m3 fp8 (8 threads/row) + zero g_rowsum
//   2) rowsum GEMM over UPPER-TRIANGLE tile chunks (symmetry): FP8 e4m3
//      mma.sync m16n8k32 (fp32 accum), 256 threads / 8 warps, 2 CTAs/SM
//      (48KB/CTA smem) so epilogue overlaps the co-resident CTA's MMAs.
//      Packed-f32x2 degree-6 exp epilogue feeds row sums + (off-diag) col
//      sums via fp32 atomicAdd into g_rowsum.
//   3) pairs+finalize (counter-fused, dequantized fp8 dots) -> out
// ---------------------------------------------------------------------------

#define C_DIM 128
#define BLK 5
#define MAX_T 4096
#define TM 128
#define NTHR 256

__device__ __align__(16) uint8_t g_xq[MAX_T * C_DIM];  // e4m3; zero-init: rows>=T are 0
__device__ float g_rowsum[MAX_T];
__device__ float g_pairpart[128];
__device__ int   g_cnt;                // zero-init; self-resetting

// smem: A 16KB @0, B tiles @16384 and @32768  -> 48KB per CTA
#define OFF_A  0
#define OFF_B0 16384
#define OFF_B1 32768
#define SMEM_DYN 49152

// ---------------- helpers ----------------
__device__ __forceinline__ uint32_t smem_u32(const void* p) {
    uint32_t a;
    asm("{ .reg .u64 t; cvta.to.shared.u64 t, %1; cvt.u32.u64 %0, t; }" : "=r"(a) : "l"(p));
    return a;
}

__device__ __forceinline__ void cp_async16(uint32_t dst, const void* src) {
    asm volatile("cp.async.cg.shared.global [%0], [%1], 16;"
                 :: "r"(dst), "l"(__cvta_generic_to_global(src)));
}
#define CP_COMMIT()  asm volatile("cp.async.commit_group;" ::: "memory")
#define CP_WAIT(n)   asm volatile("cp.async.wait_group %0;" :: "n"(n) : "memory")

__device__ __forceinline__ void ldmatrix_x4(uint32_t* r, uint32_t addr) {
    asm volatile("ldmatrix.sync.aligned.m8n8.x4.shared.b16 {%0,%1,%2,%3}, [%4];"
                 : "=r"(r[0]), "=r"(r[1]), "=r"(r[2]), "=r"(r[3]) : "r"(addr));
}

// FP8 e4m3 MMA, fp32 accumulate. A: 4 regs (16x32), B: 2 regs (32x8).
__device__ __forceinline__ void mma_fp8(float* c, const uint32_t* a,
                                        uint32_t b0, uint32_t b1) {
    asm volatile(
        "mma.sync.aligned.m16n8k32.row.col.f32.e4m3.e4m3.f32 "
        "{%0,%1,%2,%3}, {%4,%5,%6,%7}, {%8,%9}, {%0,%1,%2,%3};"
        : "+f"(c[0]), "+f"(c[1]), "+f"(c[2]), "+f"(c[3])
        : "r"(a[0]), "r"(a[1]), "r"(a[2]), "r"(a[3]), "r"(b0), "r"(b1));
}

// ---------------- fp32x2 packed math ----------------
__device__ __forceinline__ unsigned long long pk2(float lo, float hi) {
    unsigned long long r;
    asm("mov.b64 %0, {%1, %2};" : "=l"(r) : "f"(lo), "f"(hi));
    return r;
}
__device__ __forceinline__ float2 up2(unsigned long long v) {
    float2 r;
    asm("mov.b64 {%0, %1}, %2;" : "=f"(r.x), "=f"(r.y) : "l"(v));
    return r;
}
__device__ __forceinline__ unsigned long long fma2(unsigned long long a,
                                                   unsigned long long b,
                                                   unsigned long long c) {
    unsigned long long d;
    asm("fma.rn.f32x2 %0, %1, %2, %3;" : "=l"(d) : "l"(a), "l"(b), "l"(c));
    return d;
}
__device__ __forceinline__ unsigned long long add2(unsigned long long a,
                                                   unsigned long long b) {
    unsigned long long d;
    asm("add.rn.f32x2 %0, %1, %2;" : "=l"(d) : "l"(a), "l"(b));
    return d;
}
// exp(c) for |c| <= ~1.05, degree-6 Taylor; exp_pk(0) == 1.0 exactly.
__device__ __forceinline__ unsigned long long exp_pk(unsigned long long c) {
    unsigned long long p = pk2(1.3888889e-3f, 1.3888889e-3f);   // 1/6!
    p = fma2(p, c, pk2(8.3333333e-3f, 8.3333333e-3f));          // 1/5!
    p = fma2(p, c, pk2(4.1666667e-2f, 4.1666667e-2f));          // 1/4!
    p = fma2(p, c, pk2(1.6666667e-1f, 1.6666667e-1f));          // 1/3!
    p = fma2(p, c, pk2(0.5f, 0.5f));
    p = fma2(p, c, pk2(1.0f, 1.0f));
    p = fma2(p, c, pk2(1.0f, 1.0f));
    return p;
}

// pack 2 floats -> 2 e4m3 bytes (lo=f0, hi=f1)
__device__ __forceinline__ uint32_t f2_to_e4m3x2(float f0, float f1) {
    uint16_t h;
    asm("cvt.rn.satfinite.e4m3x2.f32 %0, %1, %2;" : "=h"(h) : "f"(f1), "f"(f0));
    return (uint32_t)h;
}
__device__ __forceinline__ float e4m3_to_f(uint32_t byte) {
    __nv_fp8_e4m3 t;
    t.__x = (uint8_t)byte;
    return (float)t;
}

// tile smem layout: row-major 128 rows x 128B, 16B chunks XOR-swizzled by (row&7)
__device__ __forceinline__ void copy_tile_async(uint32_t dstb, int grow0, int tid) {
    #pragma unroll
    for (int l = 0; l < 4; l++) {
        int idx = tid + l * NTHR;              // 0..1023
        int row = idx >> 3;
        int ch  = idx & 7;
        cp_async16(dstb + row * 128 + ((ch ^ (row & 7)) << 4),
                   &g_xq[(grow0 + row) * C_DIM + ch * 16]);
    }
}

// flat chunk index -> (it, jt0, njt): panel it, chunk q covers jt = it+2q, +1
__device__ __forceinline__ void job_decode(int f, int ntM, int& it, int& jt0, int& njt) {
    int i = 0;
    for (;;) {
        int pairs = (ntM - i + 1) >> 1;
        if (f < pairs) { it = i; jt0 = i + f * 2; njt = min(2, ntM - jt0); return; }
        f -= pairs; ++i;
    }
}

// ---------------- kernels ----------------
__global__ __launch_bounds__(512) void normalize_kernel(const float* __restrict__ x, int T) {
    int tid = blockIdx.x * 512 + threadIdx.x;
    if (tid < MAX_T) g_rowsum[tid] = 0.f;      // per-replay reset
    int row = tid >> 3;
    int sub = tid & 7;                         // 8 threads per row, 16 floats each
    if (row < T) {
        const float4* px = (const float4*)&x[row * C_DIM + sub * 16];
        float4 v0 = px[0], v1 = px[1], v2 = px[2], v3 = px[3];
        float s = v0.x*v0.x + v0.y*v0.y + v0.z*v0.z + v0.w*v0.w
                + v1.x*v1.x + v1.y*v1.y + v1.z*v1.z + v1.w*v1.w
                + v2.x*v2.x + v2.y*v2.y + v2.z*v2.z + v2.w*v2.w
                + v3.x*v3.x + v3.y*v3.y + v3.z*v3.z + v3.w*v3.w;
        #pragma unroll
        for (int o = 1; o < 8; o <<= 1) s += __shfl_xor_sync(0xffffffffu, s, o);
        float inv = 1.0f / fmaxf(sqrtf(s), 1e-8f);
        float4 vv[4] = {v0, v1, v2, v3};
        uint32_t w[4];
        #pragma unroll
        for (int q = 0; q < 4; q++) {
            uint32_t lo = f2_to_e4m3x2(vv[q].x * inv, vv[q].y * inv);
            uint32_t hi = f2_to_e4m3x2(vv[q].z * inv, vv[q].w * inv);
            w[q] = lo | (hi << 16);
        }
        uint4 pk; pk.x = w[0]; pk.y = w[1]; pk.z = w[2]; pk.w = w[3];
        *(uint4*)&g_xq[row * C_DIM + sub * 16] = pk;
    }
}

__global__ void __launch_bounds__(NTHR, 2) rowsum_tri(int T, int ntM) {
    extern __shared__ char smem[];
    const uint32_t sb = smem_u32(smem);
    const int tid  = threadIdx.x;
    const int wid  = tid >> 5;                 // 0..7
    const int lane = tid & 31;

    int it, jt0, njt;
    job_decode(blockIdx.x, ntM, it, jt0, njt);
    const int i0 = it * TM;

    // prefetch: group0 = {A, B0}; group1 = {B1}
    copy_tile_async(sb + OFF_A, i0, tid);
    copy_tile_async(sb + OFF_B0, jt0 * TM, tid);
    CP_COMMIT();
    if (njt == 2) {
        copy_tile_async(sb + OFF_B1, (jt0 + 1) * TM, tid);
        CP_COMMIT();
    }

    const int mq = wid >> 1;                   // M quarter: 32 rows
    const int nh = wid & 1;                    // N half: 64 cols of 128
    const int mrow = mq * 32;
    const int jloc = nh * 64;
    const int s7   = lane & 7;

    const int ro_a = (lane & 7) + ((lane >> 3) & 1) * 8;
    const int cg_a = (lane >> 4);
    const int ro_b = (lane & 7) + ((lane >> 4) & 1) * 8;
    const int cg_b = (lane >> 3) & 1;

    uint32_t a_addr[2];
    #pragma unroll
    for (int mi = 0; mi < 2; mi++)
        a_addr[mi] = sb + OFF_A + (mrow + mi * 16 + ro_a) * 128;

    for (int s = 0; s < njt; s++) {
        if (s == 0) { if (njt == 2) { CP_WAIT(1); } else { CP_WAIT(0); } }
        else        { CP_WAIT(0); }
        __syncthreads();

        const int jt  = jt0 + s;
        const int gj0 = jt * TM + jloc;
        const uint32_t bt = sb + (s ? OFF_B1 : OFF_B0);
        uint32_t b_addr[4];
        #pragma unroll
        for (int p = 0; p < 4; p++)
            b_addr[p] = bt + (jloc + p * 16 + ro_b) * 128;

        float c[2][8][4];
        #pragma unroll
        for (int mi = 0; mi < 2; mi++)
            #pragma unroll
            for (int ni = 0; ni < 8; ni++)
                #pragma unroll
                for (int q = 0; q < 4; q++) c[mi][ni][q] = 0.f;

        // K = 128 fp8 = 4 mma-ksteps of 32 (chunk pairs)
        #pragma unroll
        for (int ks = 0; ks < 4; ks++) {
            const uint32_t chA = (uint32_t)(((ks * 2 + cg_a) ^ s7) << 4);
            const uint32_t chB = (uint32_t)(((ks * 2 + cg_b) ^ s7) << 4);
            uint32_t a[2][4], b[4][4];
            #pragma unroll
            for (int mi = 0; mi < 2; mi++) ldmatrix_x4(a[mi], a_addr[mi] + chA);
            #pragma unroll
            for (int p = 0; p < 4; p++)    ldmatrix_x4(b[p], b_addr[p] + chB);
            #pragma unroll
            for (int mi = 0; mi < 2; mi++)
                #pragma unroll
                for (int ni = 0; ni < 8; ni++)
                    mma_fp8(c[mi][ni], a[mi],
                            b[ni >> 1][(ni & 1) * 2], b[ni >> 1][(ni & 1) * 2 + 1]);
        }

        // ---- epilogue: exp once; row sums + (off-diag) col sums ----
        unsigned long long racc[4] = {0ull, 0ull, 0ull, 0ull};
        unsigned long long cacc[8] = {0ull,0ull,0ull,0ull,0ull,0ull,0ull,0ull};
        #pragma unroll
        for (int mi = 0; mi < 2; mi++)
            #pragma unroll
            for (int ni = 0; ni < 8; ni++) {
                unsigned long long e01 = exp_pk(pk2(c[mi][ni][0], c[mi][ni][1]));
                unsigned long long e23 = exp_pk(pk2(c[mi][ni][2], c[mi][ni][3]));
                racc[mi * 2]     = add2(racc[mi * 2], e01);
                racc[mi * 2 + 1] = add2(racc[mi * 2 + 1], e23);
                cacc[ni]         = add2(cacc[ni], add2(e01, e23));
            }

        // row sums: subtract padded (col >= T) contributions of this lane
        int padc = 0;
        if (gj0 + 64 > T) {
            #pragma unroll
            for (int ni = 0; ni < 8; ni++) {
                int col = gj0 + ni * 8 + 2 * (lane & 3);
                padc += (col >= T) + (col + 1 >= T);
            }
        }
        float rrow[4];
        #pragma unroll
        for (int q = 0; q < 4; q++) {
            float2 u = up2(racc[q]);
            rrow[q] = (u.x + u.y) - (float)padc;
            rrow[q] += __shfl_xor_sync(0xffffffffu, rrow[q], 1);
            rrow[q] += __shfl_xor_sync(0xffffffffu, rrow[q], 2);
        }
        if ((lane & 3) == 0) {
            int rbase = i0 + mrow + (lane >> 2);
            #pragma unroll
            for (int mi = 0; mi < 2; mi++)
                #pragma unroll
                for (int h = 0; h < 2; h++) {
                    int row = rbase + mi * 16 + h * 8;
                    if (row < T) atomicAdd(&g_rowsum[row], rrow[mi * 2 + h]);
                }
        }

        // col sums (symmetry) — skip the diagonal tile
        if (jt != it) {
            float padr = (float)min(32, max(0, i0 + mrow + 32 - T));
            #pragma unroll
            for (int ni = 0; ni < 8; ni++) {
                float2 u = up2(cacc[ni]);
                #pragma unroll
                for (int o = 4; o <= 16; o <<= 1) {
                    u.x += __shfl_xor_sync(0xffffffffu, u.x, o);
                    u.y += __shfl_xor_sync(0xffffffffu, u.y, o);
                }
                if (lane < 4) {
                    int col = gj0 + ni * 8 + 2 * lane;
                    if (col < T)     atomicAdd(&g_rowsum[col],     u.x - padr);
                    if (col + 1 < T) atomicAdd(&g_rowsum[col + 1], u.y - padr);
                }
            }
        }
    }
}

// warp-per-block: in-block cosines (fp32 dots over the SAME fp8 data the GEMM
// used) + loss terms; counter-fused final reduction writes out.
__global__ __launch_bounds__(256) void pairs_finalize(
    float rscale, int Bnum, int ncta, const int* __restrict__ kuai2,
    float* __restrict__ out)
{
    const int lane = threadIdx.x & 31;
    const int wid  = threadIdx.x >> 5;
    const int b    = blockIdx.x * 8 + wid;

    float warp_term = 0.f;
    if (b < Bnum) {
        float4 u[BLK];
        #pragma unroll
        for (int m = 0; m < BLK; m++) {
            uint32_t w = *(const uint32_t*)&g_xq[(b * BLK + m) * C_DIM + lane * 4];
            u[m] = make_float4(e4m3_to_f(w & 0xff), e4m3_to_f((w >> 8) & 0xff),
                               e4m3_to_f((w >> 16) & 0xff), e4m3_to_f(w >> 24));
        }
        float cm[BLK][BLK];
        #pragma unroll
        for (int i = 0; i < BLK; i++)
            #pragma unroll
            for (int j = i; j < BLK; j++) {
                float s = u[i].x * u[j].x + u[i].y * u[j].y
                        + u[i].z * u[j].z + u[i].w * u[j].w;
                #pragma unroll
                for (int o = 16; o > 0; o >>= 1) s += __shfl_xor_sync(0xffffffffu, s, o);
                cm[i][j] = s; cm[j][i] = s;
            }
        float term = 0.f;
        if (lane < BLK) {
            int i = lane;
            float es[BLK], bsum = 0.f;
            #pragma unroll
            for (int m = 0; m < BLK; m++) { es[m] = expf(cm[i][m]); bsum += es[m]; }
            float rs = g_rowsum[b * BLK + i];
            float negA = rscale * (rs - bsum);
            #pragma unroll
            for (int m = 0; m < BLK; m++)
                if (m != i) term += logf(es[m] + negA) - cm[i][m];
        }
        #pragma unroll
        for (int o = 16; o > 0; o >>= 1) term += __shfl_xor_sync(0xffffffffu, term, o);
        warp_term = term;
    }

    __shared__ float ws[8];
    __shared__ int s_fin;
    if (lane == 0) ws[wid] = warp_term;
    __syncthreads();
    if (threadIdx.x == 0) {
        float s = 0.f;
        #pragma unroll
        for (int k = 0; k < 8; k++) s += ws[k];
        g_pairpart[blockIdx.x] = s;
        __threadfence();
        int o = atomicAdd(&g_cnt, 1);
        s_fin = (o == ncta - 1);
        if (s_fin) g_cnt = 0;                  // reset for next replay
    }
    __syncthreads();
    if (s_fin && threadIdx.x < 32) {
        __threadfence();
        double s = 0.0;
        for (int i = threadIdx.x; i < ncta; i += 32) s += (double)g_pairpart[i];
        #pragma unroll
        for (int o = 16; o > 0; o >>= 1) s += __shfl_xor_sync(0xffffffffu, s, o);
        if (threadIdx.x == 0) {
            int k2 = *kuai2;
            out[0] = (float)(s / ((double)Bnum * (double)k2 * (double)(k2 - 1)));
        }
    }
}

// ---------------- launch ----------------
extern "C" void kernel_launch(void* const* d_in, const int* in_sizes, int n_in,
                              void* d_out, int out_size) {
    const float* x     = (const float*)d_in[0];
    const int*   kuai2 = (const int*)d_in[1];

    int T = in_sizes[0] / C_DIM;
    int B = T / BLK;
    float r = (float)(2 * B - 2) / (float)(T - BLK);
    int ntM = (T + TM - 1) / TM;

    int NJ = 0;
    for (int i = 0; i < ntM; i++) NJ += (ntM - i + 1) >> 1;   // chunk count
    int ncta_pairs = (B + 7) / 8;
    int nthr_norm = ((T * 8 > MAX_T) ? T * 8 : MAX_T);

    cudaFuncSetAttribute(rowsum_tri, cudaFuncAttributeMaxDynamicSharedMemorySize, SMEM_DYN);

    normalize_kernel<<<(nthr_norm + 511) / 512, 512>>>(x, T);
    rowsum_tri<<<NJ, NTHR, SMEM_DYN>>>(T, ntM);
    pairs_finalize<<<ncta_pairs, 256>>>(r, B, ncta_pairs, kuai2, (float*)d_out);
}